// round 2
// baseline (speedup 1.0000x reference)
#include <cuda_runtime.h>

#define T_STEPS 256
#define MB      64
#define DIN     512
#define HID     1024
#define SIXH    6144
#define NROWS   (T_STEPS * MB)   /* 16384 */
#define RBLK    96               /* persistent grid size */
#define RCOLS   64               /* cols per block in recurrent GEMM */

// ---------------- scratch (static device memory; no allocs) ----------------
__device__ float g_Abuf[(size_t)NROWS * SIXH];  // x-part + bias, per layer (reused)
__device__ float g_Hbuf[(size_t)NROWS * HID];   // layer-0 hidden sequence
__device__ float g_z[MB * SIXH];                // per-step gate pre-activations
__device__ float g_h[MB * HID];                 // recurrent h state
__device__ float g_c[MB * HID];                 // recurrent c state
__device__ unsigned int g_barc;                 // grid barrier counter

// ---------------- f32x2 packed-FMA helpers (2 fp32 FMA / instr) ------------
__device__ __forceinline__ unsigned long long pack2(float x, float y) {
    unsigned long long r;
    asm("mov.b64 %0, {%1, %2};" : "=l"(r) : "f"(x), "f"(y));
    return r;
}
__device__ __forceinline__ void fma2(unsigned long long& acc,
                                     unsigned long long a, unsigned long long b) {
    asm("fma.rn.f32x2 %0, %1, %2, %0;" : "+l"(acc) : "l"(a), "l"(b));
}
__device__ __forceinline__ float2 unpack2(unsigned long long v) {
    float2 r;
    asm("mov.b64 {%0, %1}, %2;" : "=f"(r.x), "=f"(r.y) : "l"(v));
    return r;
}

__device__ __forceinline__ float sigmoidf_(float x) {
    return 1.0f / (1.0f + expf(-x));
}

// ---------------- init: zero state + barrier counter -----------------------
__global__ void zero_state() {
    int i = blockIdx.x * blockDim.x + threadIdx.x;
    if (i < MB * HID) { g_h[i] = 0.0f; g_c[i] = 0.0f; }
    if (i == 0) g_barc = 0u;
}

// ---------------- big parallel GEMM: out[M,6144] = A[M,K]@W[K,6144]+b -------
// 128x128 tile, BK=8, 256 threads, 8x8 micro-tile via f32x2 (col pairs).
__global__ void __launch_bounds__(256) gemm_big(
    const float* __restrict__ A, const float* __restrict__ W,
    const float* __restrict__ bias, float* __restrict__ out, int K)
{
    __shared__ float As[8][128];
    __shared__ float Bs[8][128];
    const int tid  = threadIdx.x;
    const int row0 = blockIdx.y * 128;
    const int col0 = blockIdx.x * 128;
    const int ty = tid >> 4, tx = tid & 15;

    const int lrow = tid >> 1;           // 0..127
    const int lk4  = (tid & 1) * 4;      // 0 or 4
    const int wkk  = tid >> 5;           // 0..7
    const int wc4  = (tid & 31) * 4;     // 0..124

    unsigned long long acc[8][4];
#pragma unroll
    for (int i = 0; i < 8; i++)
#pragma unroll
        for (int j = 0; j < 4; j++) acc[i][j] = 0ull;

    float4 av = *(const float4*)&A[(size_t)(row0 + lrow) * K + lk4];
    float4 bv = *(const float4*)&W[(size_t)wkk * SIXH + col0 + wc4];

    for (int k0 = 0; k0 < K; k0 += 8) {
        As[lk4 + 0][lrow] = av.x;
        As[lk4 + 1][lrow] = av.y;
        As[lk4 + 2][lrow] = av.z;
        As[lk4 + 3][lrow] = av.w;
        *(float4*)&Bs[wkk][wc4] = bv;
        __syncthreads();
        if (k0 + 8 < K) {   // prefetch next chunk while computing
            av = *(const float4*)&A[(size_t)(row0 + lrow) * K + k0 + 8 + lk4];
            bv = *(const float4*)&W[(size_t)(k0 + 8 + wkk) * SIXH + col0 + wc4];
        }
#pragma unroll
        for (int kk = 0; kk < 8; kk++) {
            float4 a0 = *(const float4*)&As[kk][ty * 4];
            float4 a1 = *(const float4*)&As[kk][64 + ty * 4];
            unsigned long long b[4];
            b[0] = *(const unsigned long long*)&Bs[kk][tx * 4];
            b[1] = *(const unsigned long long*)&Bs[kk][tx * 4 + 2];
            b[2] = *(const unsigned long long*)&Bs[kk][64 + tx * 4];
            b[3] = *(const unsigned long long*)&Bs[kk][64 + tx * 4 + 2];
            float af[8] = {a0.x, a0.y, a0.z, a0.w, a1.x, a1.y, a1.z, a1.w};
#pragma unroll
            for (int i = 0; i < 8; i++) {
                unsigned long long a2 = pack2(af[i], af[i]);
#pragma unroll
                for (int j = 0; j < 4; j++) fma2(acc[i][j], a2, b[j]);
            }
        }
        __syncthreads();
    }
#pragma unroll
    for (int i = 0; i < 8; i++) {
        int r = row0 + ((i < 4) ? (ty * 4 + i) : (64 + ty * 4 + (i - 4)));
        float* orow = out + (size_t)r * SIXH;
#pragma unroll
        for (int j = 0; j < 4; j++) {
            int c = col0 + ((j < 2) ? (tx * 4 + j * 2) : (64 + tx * 4 + (j - 2) * 2));
            float2 p = unpack2(acc[i][j]);
            orow[c]     = p.x + bias[c];
            orow[c + 1] = p.y + bias[c + 1];
        }
    }
}

// ---------------- grid barrier (monotonic counter, reset per launch) -------
__device__ __forceinline__ void grid_barrier(unsigned int& target) {
    __syncthreads();
    __threadfence();
    target += gridDim.x;
    if (threadIdx.x == 0) {
        atomicAdd(&g_barc, 1u);
        while (*((volatile unsigned int*)&g_barc) < target) __nanosleep(32);
    }
    __syncthreads();
}

// ---------------- recurrent step GEMM: z = h @ Wh + Abuf[t] ----------------
// Each of 96 blocks computes a 64-row x 64-col slice of z. BK=16.
__device__ __forceinline__ void step_gemm(
    const float* __restrict__ Wh, const float* __restrict__ Arow,
    int colbase, int tid, float (*Hs)[64], float (*Ws)[64])
{
    const int ty = tid >> 4, tx = tid & 15;
    const int hrow = tid >> 2;          // 0..63
    const int hk4  = (tid & 3) * 4;     // 0,4,8,12
    const int wkk  = tid >> 4;          // 0..15
    const int wc4  = (tid & 15) * 4;    // 0..60

    unsigned long long acc[4][2];
#pragma unroll
    for (int i = 0; i < 4; i++) { acc[i][0] = 0ull; acc[i][1] = 0ull; }

    float4 hv = __ldcg((const float4*)&g_h[hrow * HID + hk4]);
    float4 wv = *(const float4*)&Wh[(size_t)wkk * SIXH + colbase + wc4];

    for (int k0 = 0; k0 < HID; k0 += 16) {
        Hs[hk4 + 0][hrow] = hv.x;
        Hs[hk4 + 1][hrow] = hv.y;
        Hs[hk4 + 2][hrow] = hv.z;
        Hs[hk4 + 3][hrow] = hv.w;
        *(float4*)&Ws[wkk][wc4] = wv;
        __syncthreads();
        if (k0 + 16 < HID) {  // prefetch
            hv = __ldcg((const float4*)&g_h[hrow * HID + k0 + 16 + hk4]);
            wv = *(const float4*)&Wh[(size_t)(k0 + 16 + wkk) * SIXH + colbase + wc4];
        }
#pragma unroll
        for (int kk = 0; kk < 16; kk++) {
            float4 a = *(const float4*)&Hs[kk][ty * 4];
            unsigned long long b0 = *(const unsigned long long*)&Ws[kk][tx * 4];
            unsigned long long b1 = *(const unsigned long long*)&Ws[kk][tx * 4 + 2];
            unsigned long long r0 = pack2(a.x, a.x);
            unsigned long long r1 = pack2(a.y, a.y);
            unsigned long long r2 = pack2(a.z, a.z);
            unsigned long long r3 = pack2(a.w, a.w);
            fma2(acc[0][0], r0, b0); fma2(acc[0][1], r0, b1);
            fma2(acc[1][0], r1, b0); fma2(acc[1][1], r1, b1);
            fma2(acc[2][0], r2, b0); fma2(acc[2][1], r2, b1);
            fma2(acc[3][0], r3, b0); fma2(acc[3][1], r3, b1);
        }
        __syncthreads();
    }
#pragma unroll
    for (int i = 0; i < 4; i++) {
        int r = ty * 4 + i;
        int c = colbase + tx * 4;
        float2 p0 = unpack2(acc[i][0]);
        float2 p1 = unpack2(acc[i][1]);
        const float* arow = Arow + (size_t)r * SIXH;
        float* zr = g_z + (size_t)r * SIXH;
        zr[c]     = p0.x + arow[c];
        zr[c + 1] = p0.y + arow[c + 1];
        zr[c + 2] = p1.x + arow[c + 2];
        zr[c + 3] = p1.y + arow[c + 3];
    }
}

// ---------------- cummax(seg) = cumsum(softmax(seg)) over 1024 -------------
// 256 threads, 4 contiguous elems/thread; out = inclusive prefixes.
__device__ void cummax_seg(const float* __restrict__ seg, int tid,
                           float out[4], volatile float* s_red)
{
    const int lane = tid & 31, warp = tid >> 5;
    float4 v = __ldcg((const float4*)(seg + tid * 4));
    float mx = fmaxf(fmaxf(v.x, v.y), fmaxf(v.z, v.w));
#pragma unroll
    for (int off = 16; off > 0; off >>= 1)
        mx = fmaxf(mx, __shfl_xor_sync(0xffffffffu, mx, off));
    if (lane == 0) s_red[warp] = mx;
    __syncthreads();
    float bm = s_red[0];
#pragma unroll
    for (int w = 1; w < 8; w++) bm = fmaxf(bm, s_red[w]);
    __syncthreads();

    float e0 = expf(v.x - bm), e1 = expf(v.y - bm);
    float e2 = expf(v.z - bm), e3 = expf(v.w - bm);
    float p1 = e0 + e1, p2 = p1 + e2, p3 = p2 + e3;
    float sc = p3;
#pragma unroll
    for (int off = 1; off < 32; off <<= 1) {
        float n = __shfl_up_sync(0xffffffffu, sc, off);
        if (lane >= off) sc += n;
    }
    if (lane == 31) s_red[warp] = sc;
    __syncthreads();
    float woff = 0.0f, tot = 0.0f;
#pragma unroll
    for (int w = 0; w < 8; w++) {
        float x = s_red[w];
        tot += x;
        if (w < warp) woff += x;
    }
    __syncthreads();
    float base = woff + (sc - p3);   // exclusive prefix for this thread
    float inv = 1.0f / tot;
    out[0] = (base + e0) * inv;
    out[1] = (base + p1) * inv;
    out[2] = (base + p2) * inv;
    out[3] = (base + p3) * inv;
}

// ---------------- per-row gate math + state update -------------------------
__device__ void step_gate(int t, int m, int tid,
                          float* __restrict__ hout,
                          float* __restrict__ hn, float* __restrict__ cn,
                          volatile float* s_red)
{
    const float* zrow = g_z + (size_t)m * SIXH;
    float ftl[4], icum[4];
    cummax_seg(zrow + 4 * HID, tid, ftl, s_red);   // ftilde segment
    cummax_seg(zrow + 5 * HID, tid, icum, s_red);  // itilde segment

    const int j0 = tid * 4;
    float4 zi = __ldcg((const float4*)(zrow + j0));
    float4 zf = __ldcg((const float4*)(zrow + HID + j0));
    float4 zg = __ldcg((const float4*)(zrow + 2 * HID + j0));
    float4 zo = __ldcg((const float4*)(zrow + 3 * HID + j0));
    float zia[4] = {zi.x, zi.y, zi.z, zi.w};
    float zfa[4] = {zf.x, zf.y, zf.z, zf.w};
    float zga[4] = {zg.x, zg.y, zg.z, zg.w};
    float zoa[4] = {zo.x, zo.y, zo.z, zo.w};

    const size_t sbase = (size_t)m * HID + j0;
    const size_t obase = (size_t)(t * MB + m) * HID + j0;
#pragma unroll
    for (int i = 0; i < 4; i++) {
        float ft = ftl[i];
        float it = 1.0f - icum[i];
        float omega = ft * it;
        float fg = sigmoidf_(zfa[i]);
        float ig = sigmoidf_(zia[i]);
        float og = sigmoidf_(zoa[i]);
        float ch = tanhf(zga[i]);
        float fhat = fg * omega + (ft - omega);
        float ihat = ig * omega + (it - omega);
        float cold = g_c[sbase + i];
        float cnew = fhat * cold + ihat * ch;
        float hnew = og * tanhf(cnew);
        g_c[sbase + i] = cnew;
        g_h[sbase + i] = hnew;
        hout[obase + i] = hnew;
        if (t == T_STEPS - 1) {
            hn[sbase + i] = hnew;
            cn[sbase + i] = cnew;
        }
    }
}

// ---------------- persistent recurrent kernel (96 blocks, 256 thr) ---------
__global__ void __launch_bounds__(256) recurrent(
    const float* __restrict__ Wh, const float* __restrict__ Abase,
    float* __restrict__ hout, float* __restrict__ hn, float* __restrict__ cn)
{
    __shared__ float Hs[16][64];
    __shared__ float Ws[16][64];
    __shared__ float s_red[8];
    const int tid = threadIdx.x;
    const int colbase = blockIdx.x * RCOLS;
    unsigned int bar_target = 0;

    for (int t = 0; t < T_STEPS; t++) {
        step_gemm(Wh, Abase + (size_t)t * MB * SIXH, colbase, tid, Hs, Ws);
        grid_barrier(bar_target);
        if (blockIdx.x < MB)
            step_gate(t, blockIdx.x, tid, hout, hn, cn, (volatile float*)s_red);
        grid_barrier(bar_target);
    }
}

// ---------------- launch --------------------------------------------------
extern "C" void kernel_launch(void* const* d_in, const int* in_sizes, int n_in,
                              void* d_out, int out_size)
{
    const float* X  = (const float*)d_in[0];   // [256,64,512]
    const float* W0 = (const float*)d_in[1];   // [1536,6144]
    const float* b0 = (const float*)d_in[2];   // [6144]
    const float* W1 = (const float*)d_in[3];   // [2048,6144]
    const float* b1 = (const float*)d_in[4];   // [6144]
    float* out = (float*)d_out;

    float *Abuf = nullptr, *Hbuf = nullptr;
    cudaGetSymbolAddress((void**)&Abuf, g_Abuf);
    cudaGetSymbolAddress((void**)&Hbuf, g_Hbuf);

    float* allh = out;                                   // [256,64,1024]
    float* hn   = out + (size_t)NROWS * HID;             // [2,64,1024]
    float* cn   = hn + 2 * MB * HID;                     // [2,64,1024]

    dim3 gbig(SIXH / 128, NROWS / 128);   // (48, 128)

    // ---- layer 0 ----
    zero_state<<<256, 256>>>();
    gemm_big<<<gbig, 256>>>(X, W0, b0, Abuf, DIN);
    recurrent<<<RBLK, 256>>>(W0 + (size_t)DIN * SIXH, Abuf, Hbuf,
                             hn, cn);
    // ---- layer 1 ----
    zero_state<<<256, 256>>>();
    gemm_big<<<gbig, 256>>>(Hbuf, W1, b1, Abuf, HID);
    recurrent<<<RBLK, 256>>>(W1 + (size_t)HID * SIXH, Abuf, allh,
                             hn + MB * HID, cn + MB * HID);
}